// round 16
// baseline (speedup 1.0000x reference)
#include <cuda_runtime.h>
#include <cuda_fp16.h>
#include <cstdint>

#define BLD   1024
#define DIM   768
#define LSEQ  512
#define NSTATE 16
#define NVOC  50257

// ---------------- fp32 scratch ----------------------------------------------
__device__ float g_x [BLD*DIM];
__device__ float g_xr[BLD*2*DIM];
__device__ float g_xc[BLD*DIM];
__device__ float g_dt[BLD*DIM];
// ---------------- split-fp16 activations -------------------------------------
__device__ __half g_ah_xn[BLD*DIM], g_al_xn[BLD*DIM];
__device__ __half g_ah_xc[BLD*DIM], g_al_xc[BLD*DIM];
__device__ __half g_ah_y [BLD*DIM], g_al_y [BLD*DIM];
// ---------------- fp16 weights (hi only — NT2 layers / NT1 head) --------------
__device__ __half g_wh_in [4*2*DIM*DIM];
__device__ __half g_wh_dt [4*DIM*DIM];
__device__ __half g_wh_out[4*DIM*DIM];
__device__ __half g_wh_hd [NVOC*DIM];

__device__ __forceinline__ float fast_sigmoid(float z) {
    return 1.0f / (1.0f + __expf(-z));
}
__device__ __forceinline__ void split_store(__half* ph, __half* pl, size_t i, float v) {
    __half h = __float2half_rn(v);
    ph[i] = h;
    pl[i] = __float2half_rn(v - __half2float(h));
}

// ---------------- merged weight fp16 prepass (all 4 tensors, one launch) -------
#define N4_IN  (4 * 2 * DIM * DIM / 4)
#define N4_DT  (4 * DIM * DIM / 4)
#define N4_HD  (NVOC * DIM / 4)
#define N4_TOT (N4_IN + 2 * N4_DT + N4_HD)

__global__ void wsplit_all_kernel(const float4* __restrict__ in_w,
                                  const float4* __restrict__ dt_w,
                                  const float4* __restrict__ out_w,
                                  const float4* __restrict__ head_w,
                                  uint2* __restrict__ d_in, uint2* __restrict__ d_dt,
                                  uint2* __restrict__ d_out, uint2* __restrict__ d_hd) {
    int i = blockIdx.x * blockDim.x + threadIdx.x;
    if (i >= N4_TOT) return;
    const float4* src;
    uint2* dst;
    int j = i;
    if (j < N4_HD) {
        src = head_w; dst = d_hd;
    } else if ((j -= N4_HD) < N4_IN) {
        src = in_w; dst = d_in;
    } else if ((j -= N4_IN) < N4_DT) {
        src = dt_w; dst = d_dt;
    } else {
        j -= N4_DT;
        src = out_w; dst = d_out;
    }
    float4 v = src[j];
    __half2 h01 = __floats2half2_rn(v.x, v.y);
    __half2 h23 = __floats2half2_rn(v.z, v.w);
    dst[j] = make_uint2(*(unsigned*)&h01, *(unsigned*)&h23);
}

// ---------------- layernorm -> split fp16 (optionally fused embed gather) ------
template <int EMBED>
__global__ void ln_kernel(const float* __restrict__ x,
                          const int* __restrict__ tokens,
                          const float* __restrict__ emb,
                          const float* __restrict__ g,
                          const float* __restrict__ b,
                          __half* __restrict__ oh, __half* __restrict__ ol) {
    int row = blockIdx.x;
    const float* xp;
    if (EMBED) {
        int tok = tokens[row];
        xp = emb + (size_t)tok * DIM;
        float4* dst = (float4*)(g_x + (size_t)row * DIM);
        const float4* src = (const float4*)xp;
        for (int i = threadIdx.x; i < DIM / 4; i += 256) dst[i] = src[i];
    } else {
        xp = x + (size_t)row * DIM;
    }
    float s = 0.f, s2 = 0.f;
    for (int i = threadIdx.x; i < DIM; i += 256) {
        float v = xp[i];
        s += v; s2 += v * v;
    }
#pragma unroll
    for (int o = 16; o; o >>= 1) {
        s  += __shfl_xor_sync(0xffffffffu, s,  o);
        s2 += __shfl_xor_sync(0xffffffffu, s2, o);
    }
    __shared__ float sh[16];
    int w = threadIdx.x >> 5, lane = threadIdx.x & 31;
    if (lane == 0) { sh[w] = s; sh[8 + w] = s2; }
    __syncthreads();
    s = 0.f; s2 = 0.f;
#pragma unroll
    for (int i = 0; i < 8; i++) { s += sh[i]; s2 += sh[8 + i]; }
    float m   = s * (1.0f / DIM);
    float var = s2 * (1.0f / DIM) - m * m;
    float inv = rsqrtf(var + 1e-5f);
    for (int i = threadIdx.x; i < DIM; i += 256) {
        float v = (xp[i] - m) * inv * g[i] + b[i];
        split_store(oh, ol, (size_t)row * DIM + i, v);
    }
}

// ---------------- depthwise conv(3) + silu, float4-vectorized ------------------
__global__ void conv_silu_kernel(const float* __restrict__ cw,
                                 const float* __restrict__ cb) {
    int idx4 = blockIdx.x * blockDim.x + threadIdx.x;   // over BLD*DIM/4
    if (idx4 >= BLD * DIM / 4) return;
    int d4 = (idx4 % (DIM / 4)) * 4;
    int l  = (idx4 / (DIM / 4)) % LSEQ;
    int b  = idx4 / ((DIM / 4) * LSEQ);
    const float* base = g_xr + (size_t)b * LSEQ * (2 * DIM) + d4;
    float4 zr = make_float4(0.f, 0.f, 0.f, 0.f);
    float4 xm = (l > 0)        ? *(const float4*)(base + (size_t)(l - 1) * 2 * DIM) : zr;
    float4 x0 =                  *(const float4*)(base + (size_t)l       * 2 * DIM);
    float4 xp = (l < LSEQ - 1) ? *(const float4*)(base + (size_t)(l + 1) * 2 * DIM) : zr;
    float vm[4] = {xm.x, xm.y, xm.z, xm.w};
    float v0[4] = {x0.x, x0.y, x0.z, x0.w};
    float vp[4] = {xp.x, xp.y, xp.z, xp.w};
    float out[4];
#pragma unroll
    for (int j = 0; j < 4; j++) {
        int d = d4 + j;
        float z = vm[j] * cw[d * 3 + 0] + v0[j] * cw[d * 3 + 1]
                + vp[j] * cw[d * 3 + 2] + cb[d];
        out[j] = z * fast_sigmoid(z);
    }
    size_t o = (size_t)b * LSEQ * DIM + (size_t)l * DIM + d4;
    *(float4*)(g_xc + o) = make_float4(out[0], out[1], out[2], out[3]);
    __half2 h01 = __floats2half2_rn(out[0], out[1]);
    __half2 h23 = __floats2half2_rn(out[2], out[3]);
    float2 f01 = __half22float2(h01), f23 = __half22float2(h23);
    __half2 l01 = __floats2half2_rn(out[0] - f01.x, out[1] - f01.y);
    __half2 l23 = __floats2half2_rn(out[2] - f23.x, out[3] - f23.y);
    *(uint2*)(g_ah_xc + o) = make_uint2(*(unsigned*)&h01, *(unsigned*)&h23);
    *(uint2*)(g_al_xc + o) = make_uint2(*(unsigned*)&l01, *(unsigned*)&l23);
}

// ------- selective scan: pipelined loads + BATCHED shfl reductions -------------
#define SCH 8
__global__ void scan_kernel(const float* __restrict__ A_log,
                            const float* __restrict__ Dp) {
    int tid = blockIdx.x * blockDim.x + threadIdx.x;   // 24576
    int s = tid & (NSTATE - 1);
    int d = (tid >> 4) % DIM;
    int b = tid / (DIM * NSTATE);
    float A  = -__expf(A_log[d * NSTATE + s]);
    float Dd = Dp[d];
    const float* dtp  = g_dt + (size_t)b * LSEQ * DIM + d;
    const float* xcp  = g_xc + (size_t)b * LSEQ * DIM + d;
    const float* resp = g_xr + (size_t)b * LSEQ * (2 * DIM) + DIM + d;
    size_t ybase = (size_t)b * LSEQ * DIM + d;

    float dbuf[2][SCH], xbuf[2][SCH], rbuf[2][SCH];
#pragma unroll
    for (int c = 0; c < SCH; c++) {
        dbuf[0][c] = dtp[(size_t)c * DIM];
        xbuf[0][c] = xcp[(size_t)c * DIM];
        rbuf[0][c] = resp[(size_t)c * 2 * DIM];
    }
    float h = 0.f;

#define SCAN_CHUNK(BUF, L0) do {                                               \
        float sums[SCH];                                                       \
        _Pragma("unroll")                                                      \
        for (int c = 0; c < SCH; c++) {                                        \
            float e = __expf(A * dbuf[BUF][c]);                                \
            h = h * e + xbuf[BUF][c];                                          \
            sums[c] = h;                                                       \
        }                                                                      \
        _Pragma("unroll")                                                      \
        for (int o = 1; o <= 8; o <<= 1) {                                     \
            _Pragma("unroll")                                                  \
            for (int c = 0; c < SCH; c++)                                      \
                sums[c] += __shfl_xor_sync(0xffffffffu, sums[c], o);           \
        }                                                                      \
        if (s == 0) {                                                          \
            _Pragma("unroll")                                                  \
            for (int c = 0; c < SCH; c++) {                                    \
                float r = rbuf[BUF][c];                                        \
                float v = sums[c] * Dd * (r * fast_sigmoid(r));                \
                split_store(g_ah_y, g_al_y,                                    \
                            ybase + (size_t)((L0) + c) * DIM, v);              \
            }                                                                  \
        }                                                                      \
    } while (0)
#define SCAN_PREF(BUF, CH)                                                     \
    if ((CH) < LSEQ / SCH) {                                                   \
        int base = (CH) * SCH;                                                 \
        _Pragma("unroll")                                                      \
        for (int c = 0; c < SCH; c++) {                                        \
            dbuf[BUF][c] = dtp[(size_t)(base + c) * DIM];                      \
            xbuf[BUF][c] = xcp[(size_t)(base + c) * DIM];                      \
            rbuf[BUF][c] = resp[(size_t)(base + c) * 2 * DIM];                 \
        }                                                                      \
    }

#pragma unroll 1
    for (int ch = 0; ch < LSEQ / SCH; ch += 2) {
        SCAN_PREF(1, ch + 1);
        SCAN_CHUNK(0, ch * SCH);
        SCAN_PREF(0, ch + 2);
        SCAN_CHUNK(1, (ch + 1) * SCH);
    }
#undef SCAN_CHUNK
#undef SCAN_PREF
}

// ---------------- shared MMA primitives -----------------------------------------
__device__ __forceinline__ void ldsm4(unsigned r[4], unsigned a) {
    asm volatile("ldmatrix.sync.aligned.m8n8.x4.shared.b16 {%0,%1,%2,%3}, [%4];"
                 : "=r"(r[0]), "=r"(r[1]), "=r"(r[2]), "=r"(r[3]) : "r"(a));
}
__device__ __forceinline__ void mma_f16(float c[4], const unsigned a[4],
                                        const unsigned b[2]) {
    asm volatile(
        "mma.sync.aligned.m16n8k16.row.col.f32.f16.f16.f32 "
        "{%0,%1,%2,%3}, {%4,%5,%6,%7}, {%8,%9}, {%0,%1,%2,%3};"
        : "+f"(c[0]), "+f"(c[1]), "+f"(c[2]), "+f"(c[3])
        : "r"(a[0]), "r"(a[1]), "r"(a[2]), "r"(a[3]), "r"(b[0]), "r"(b[1]));
}
__device__ __forceinline__ void cpa16(unsigned dst, const void* src, int sz) {
    asm volatile("cp.async.cg.shared.global [%0], [%1], 16, %2;"
                 :: "r"(dst), "l"(src), "r"(sz));
}

// ===== 128x128-tile head GEMM: 512 thr, NT=1 (AhBh only), 4 stages =============
#define NSTGH 4
template <int MODE>
__global__ void __launch_bounds__(512)
gemm_head(const __half* __restrict__ Ah, const __half* __restrict__ Bh,
          float* __restrict__ C, int N, int K) {
    constexpr unsigned STAGE_B = 20480u;
    extern __shared__ char smc[];
    unsigned sbase = (unsigned)__cvta_generic_to_shared(smc);
    int tid = threadIdx.x, lane = tid & 31, warp = tid >> 5;
    int wm = warp >> 2, wn = warp & 3;
    int bm = blockIdx.x * 128, bn = blockIdx.y * 128;

    unsigned aoff[2][2];
#pragma unroll
    for (int mi = 0; mi < 2; mi++)
#pragma unroll
        for (int ks = 0; ks < 2; ks++) {
            int row = wm * 32 + mi * 16 + (lane & 15);
            int col = ks * 16 + ((lane & 16) ? 8 : 0);
            aoff[mi][ks] = (unsigned)(row * 40 + col) * 2;
        }
    unsigned boff[4];
#pragma unroll
    for (int ni = 0; ni < 4; ni++) {
        int row = wn * 32 + ni * 8 + (lane & 7);
        int col = (lane >> 3) * 8;
        boff[ni] = 10240u + (unsigned)(row * 40 + col) * 2;
    }

    int r  = tid >> 2;
    int cc = (tid & 3) * 8;

    float acc[2][4][4];
#pragma unroll
    for (int mi = 0; mi < 2; mi++)
#pragma unroll
        for (int ni = 0; ni < 4; ni++)
#pragma unroll
            for (int q = 0; q < 4; q++) acc[mi][ni][q] = 0.f;

    int T = K / 32;
    int brow = bn + r;
    int crow = brow < N ? brow : (N - 1);
    int bsz  = brow < N ? 16 : 0;

#define FETCH(s, kt) do {                                                      \
        int k0 = (kt) * 32;                                                    \
        unsigned dst = sbase + (unsigned)(s) * STAGE_B +                       \
                       (unsigned)(r * 40 + cc) * 2;                            \
        cpa16(dst,           Ah + (size_t)(bm + r) * K + k0 + cc, 16);         \
        cpa16(dst + 10240u,  Bh + (size_t)crow * K + k0 + cc, bsz);            \
    } while (0)

    FETCH(0, 0);
    asm volatile("cp.async.commit_group;" ::: "memory");
    FETCH(1, 1);
    asm volatile("cp.async.commit_group;" ::: "memory");
    FETCH(2, 2);
    asm volatile("cp.async.commit_group;" ::: "memory");

    for (int i = 0; i < T; i++) {
        asm volatile("cp.async.wait_group 2;" ::: "memory");
        __syncthreads();

        if (i + 3 < T) FETCH((i + 3) & (NSTGH - 1), i + 3);
        asm volatile("cp.async.commit_group;" ::: "memory");

        unsigned st = sbase + (unsigned)(i & (NSTGH - 1)) * STAGE_B;
        unsigned Bf[4][4];
#pragma unroll
        for (int ni = 0; ni < 4; ni++) ldsm4(Bf[ni], st + boff[ni]);
#pragma unroll
        for (int ks = 0; ks < 2; ks++) {
            unsigned Af[2][4];
#pragma unroll
            for (int mi = 0; mi < 2; mi++) ldsm4(Af[mi], st + aoff[mi][ks]);
#pragma unroll
            for (int mi = 0; mi < 2; mi++)
#pragma unroll
                for (int ni = 0; ni < 4; ni++)
                    mma_f16(acc[mi][ni], Af[mi], &Bf[ni][2 * ks]);
        }
    }
#undef FETCH

#pragma unroll
    for (int mi = 0; mi < 2; mi++) {
        int rr = bm + wm * 32 + mi * 16 + (lane >> 2);
#pragma unroll
        for (int ni = 0; ni < 4; ni++) {
            int c0 = bn + wn * 32 + ni * 8 + (lane & 3) * 2;
            float* p0 = C + (size_t)rr * N + c0;
            float* p1 = C + (size_t)(rr + 8) * N + c0;
            if (c0 < N)     { p0[0] = acc[mi][ni][0]; p1[0] = acc[mi][ni][2]; }
            if (c0 + 1 < N) { p0[1] = acc[mi][ni][1]; p1[1] = acc[mi][ni][3]; }
        }
    }
}

// ===== 64x64-tile layer GEMM: 256 thr, NT=2, 3 stages -> 4 CTAs/SM =============
#define NSTG64  3
#define STAGE64 15360u           // Ah(5120) Al(5120) Bh(5120)
#define SMEM64  (NSTG64 * 15360)

template <int MODE>
__global__ void __launch_bounds__(256)
gemm64(const __half* __restrict__ Ah, const __half* __restrict__ Al,
       const __half* __restrict__ Bh,
       const float* __restrict__ bias, float* __restrict__ C,
       int N, int K) {
    extern __shared__ char smc[];
    unsigned sbase = (unsigned)__cvta_generic_to_shared(smc);
    int tid = threadIdx.x, lane = tid & 31, warp = tid >> 5;
    int wm = warp >> 2, wn = warp & 3;            // 2x4 warp grid
    int bm = blockIdx.x * 64, bn = blockIdx.y * 64;

    unsigned aoff[2][2];
#pragma unroll
    for (int mi = 0; mi < 2; mi++)
#pragma unroll
        for (int ks = 0; ks < 2; ks++) {
            int row = wm * 32 + mi * 16 + (lane & 15);
            int col = ks * 16 + ((lane & 16) ? 8 : 0);
            aoff[mi][ks] = (unsigned)(row * 40 + col) * 2;
        }
    unsigned boff[2];
#pragma unroll
    for (int ni = 0; ni < 2; ni++) {
        int row = wn * 16 + ni * 8 + (lane & 7);
        int col = (lane >> 3) * 8;
        boff[ni] = 10240u + (unsigned)(row * 40 + col) * 2;
    }

    int r  = tid >> 2;               // 0..63
    int cc = (tid & 3) * 8;

    float acc[2][2][4];
#pragma unroll
    for (int mi = 0; mi < 2; mi++)
#pragma unroll
        for (int ni = 0; ni < 2; ni++)
#pragma unroll
            for (int q = 0; q < 4; q++) acc[mi][ni][q] = 0.f;

    int T = K / 32;

#define FETCH64(s, kt) do {                                                    \
        int k0 = (kt) * 32;                                                    \
        unsigned dst = sbase + (unsigned)(s) * STAGE64 +                       \
                       (unsigned)(r * 40 + cc) * 2;                            \
        cpa16(dst,           Ah + (size_t)(bm + r) * K + k0 + cc, 16);         \
        cpa16(dst + 5120u,   Al + (size_t)(bm + r) * K + k0 + cc, 16);         \
        cpa16(dst + 10240u,  Bh + (size_t)(bn + r) * K + k0 + cc, 16);         \
    } while (0)

    FETCH64(0, 0);
    asm volatile("cp.async.commit_group;" ::: "memory");
    FETCH64(1, 1);
    asm volatile("cp.async.commit_group;" ::: "memory");

    for (int i = 0; i < T; i++) {
        asm volatile("cp.async.wait_group 1;" ::: "memory");   // stage i landed
        __syncthreads();

        // write slot (i+2)%3 == (i-1)%3: readers finished in iter i-1,
        // ordered by this iteration's barrier above.
        if (i + 2 < T) FETCH64((i + 2) % NSTG64, i + 2);
        asm volatile("cp.async.commit_group;" ::: "memory");

        unsigned st = sbase + (unsigned)(i % NSTG64) * STAGE64;
        unsigned Bhf[2][4];
#pragma unroll
        for (int ni = 0; ni < 2; ni++) ldsm4(Bhf[ni], st + boff[ni]);
#pragma unroll
        for (int ks = 0; ks < 2; ks++) {
            unsigned Ahf[2][4], Alf[2][4];
#pragma unroll
            for (int mi = 0; mi < 2; mi++) {
                ldsm4(Ahf[mi], st + aoff[mi][ks]);
                ldsm4(Alf[mi], st + aoff[mi][ks] + 5120u);
            }
#pragma unroll
            for (int mi = 0; mi < 2; mi++)
#pragma unroll
                for (int ni = 0; ni < 2; ni++) {
                    mma_f16(acc[mi][ni], Ahf[mi], &Bhf[ni][2 * ks]);
                    mma_f16(acc[mi][ni], Alf[mi], &Bhf[ni][2 * ks]);
                }
        }
    }
#undef FETCH64

#pragma unroll
    for (int mi = 0; mi < 2; mi++) {
        int rr = bm + wm * 32 + mi * 16 + (lane >> 2);
#pragma unroll
        for (int ni = 0; ni < 2; ni++) {
            int c0 = bn + wn * 16 + ni * 8 + (lane & 3) * 2;
            float* p0 = C + (size_t)rr * N + c0;
            float* p1 = C + (size_t)(rr + 8) * N + c0;
            float v0 = acc[mi][ni][0], v1 = acc[mi][ni][1];
            float v2 = acc[mi][ni][2], v3 = acc[mi][ni][3];
            if (MODE == 1) {
                float b0 = bias[c0], b1 = bias[c0 + 1];
                v0 = fast_sigmoid(v0 + b0); v1 = fast_sigmoid(v1 + b1);
                v2 = fast_sigmoid(v2 + b0); v3 = fast_sigmoid(v3 + b1);
            }
            if (MODE == 2) {
                p0[0] += v0; p0[1] += v1; p1[0] += v2; p1[1] += v3;
            } else {
                p0[0] = v0; p0[1] = v1; p1[0] = v2; p1[1] = v3;
            }
        }
    }
}

#define SMEMH (NSTGH * 20480)

// ---------------- driver ---------------------------------------------------------
extern "C" void kernel_launch(void* const* d_in, const int* in_sizes, int n_in,
                              void* d_out, int out_size) {
    const int*   tokens = (const int*)  d_in[0];
    const float* emb    = (const float*)d_in[1];
    const float* ln_g   = (const float*)d_in[2];
    const float* ln_b   = (const float*)d_in[3];
    const float* in_w   = (const float*)d_in[4];
    const float* conv_w = (const float*)d_in[5];
    const float* conv_b = (const float*)d_in[6];
    const float* dt_w   = (const float*)d_in[7];
    const float* dt_b   = (const float*)d_in[8];
    const float* A_log  = (const float*)d_in[9];
    const float* D_par  = (const float*)d_in[10];
    const float* out_w  = (const float*)d_in[11];
    const float* lnf_g  = (const float*)d_in[12];
    const float* lnf_b  = (const float*)d_in[13];
    const float* head_w = (const float*)d_in[14];
    float* out = (float*)d_out;

    float *x, *xr, *xc, *dt;
    cudaGetSymbolAddress((void**)&x,  g_x);
    cudaGetSymbolAddress((void**)&xr, g_xr);
    cudaGetSymbolAddress((void**)&xc, g_xc);
    cudaGetSymbolAddress((void**)&dt, g_dt);
    __half *ah_xn, *al_xn, *ah_xc, *al_xc, *ah_y, *al_y;
    cudaGetSymbolAddress((void**)&ah_xn, g_ah_xn);
    cudaGetSymbolAddress((void**)&al_xn, g_al_xn);
    cudaGetSymbolAddress((void**)&ah_xc, g_ah_xc);
    cudaGetSymbolAddress((void**)&al_xc, g_al_xc);
    cudaGetSymbolAddress((void**)&ah_y,  g_ah_y);
    cudaGetSymbolAddress((void**)&al_y,  g_al_y);
    __half *wh_in, *wh_dt, *wh_out, *wh_hd;
    cudaGetSymbolAddress((void**)&wh_in,  g_wh_in);
    cudaGetSymbolAddress((void**)&wh_dt,  g_wh_dt);
    cudaGetSymbolAddress((void**)&wh_out, g_wh_out);
    cudaGetSymbolAddress((void**)&wh_hd,  g_wh_hd);

    cudaFuncSetAttribute(gemm64<0>, cudaFuncAttributeMaxDynamicSharedMemorySize, SMEM64);
    cudaFuncSetAttribute(gemm64<1>, cudaFuncAttributeMaxDynamicSharedMemorySize, SMEM64);
    cudaFuncSetAttribute(gemm64<2>, cudaFuncAttributeMaxDynamicSharedMemorySize, SMEM64);
    cudaFuncSetAttribute(gemm_head<0>, cudaFuncAttributeMaxDynamicSharedMemorySize, SMEMH);

    // single merged prepass: all four weight tensors in one full-chip wave
    wsplit_all_kernel<<<(N4_TOT + 255) / 256, 256>>>(
        (const float4*)in_w, (const float4*)dt_w,
        (const float4*)out_w, (const float4*)head_w,
        (uint2*)wh_in, (uint2*)wh_dt, (uint2*)wh_out, (uint2*)wh_hd);

    for (int l = 0; l < 4; l++) {
        if (l == 0) {
            ln_kernel<1><<<BLD, 256>>>(nullptr, tokens, emb,
                                       ln_g, ln_b, ah_xn, al_xn);
        } else {
            ln_kernel<0><<<BLD, 256>>>(x, nullptr, nullptr,
                                       ln_g + l * DIM, ln_b + l * DIM,
                                       ah_xn, al_xn);
        }
        gemm64<0><<<dim3(16, 24), 256, SMEM64>>>(
            ah_xn, al_xn, wh_in + (size_t)l * 2 * DIM * DIM,
            nullptr, xr, 2 * DIM, DIM);
        conv_silu_kernel<<<(BLD * DIM / 4 + 255) / 256, 256>>>(conv_w + l * DIM * 3,
                                                               conv_b + l * DIM);
        gemm64<1><<<dim3(16, 12), 256, SMEM64>>>(
            ah_xc, al_xc, wh_dt + (size_t)l * DIM * DIM,
            dt_b + l * DIM, dt, DIM, DIM);
        scan_kernel<<<96, 256>>>(A_log + l * DIM * NSTATE, D_par + l * DIM);
        gemm64<2><<<dim3(16, 12), 256, SMEM64>>>(
            ah_y, al_y, wh_out + (size_t)l * DIM * DIM,
            nullptr, x, DIM, DIM);
    }

    ln_kernel<0><<<BLD, 256>>>(x, nullptr, nullptr, lnf_g, lnf_b, ah_xn, al_xn);
    gemm_head<0><<<dim3(8, (NVOC + 127) / 128), 512, SMEMH>>>(
        ah_xn, wh_hd, out, NVOC, DIM);
    (void)in_sizes; (void)n_in; (void)out_size;
}